// round 3
// baseline (speedup 1.0000x reference)
#include <cuda_runtime.h>
#include <cuda_bf16.h>
#include <cstdint>

#define DEV_INLINE __device__ __forceinline__

static constexpr int N_FEAT = 131072;
static constexpr int DIM    = 128;
static constexpr int K_CENT = 1024;

static constexpr int M_TILE   = 256;    // rows per CTA (8 warps x 32 rows)
static constexpr int NC_CHUNK = 128;    // centers per smem chunk
static constexpr int NUM_CHUNKS = K_CENT / NC_CHUNK;   // 8

static constexpr int ROW_BYTES = 272;   // 128 bf16 (256B) + 16B pad -> conflict-free ldmatrix
static constexpr int SMEM_A_BYTES = M_TILE * ROW_BYTES;    // 69632
static constexpr int SMEM_B_BYTES = NC_CHUNK * ROW_BYTES;  // 34816
static constexpr int SMEM_TOTAL   = SMEM_A_BYTES + SMEM_B_BYTES;  // 104448

static constexpr int LOSS_BLOCKS = 512;

// ---------------- device scratch (no allocations allowed) ----------------
__device__ __nv_bfloat16 g_cb[(size_t)K_CENT * DIM];  // normalized centers, bf16
__device__ int           g_assign[N_FEAT];
__device__ double        g_partial[LOSS_BLOCKS];

// ---------------- helpers ----------------
DEV_INLINE uint32_t smem_u32(const void* p) {
    uint32_t a;
    asm("{ .reg .u64 t; cvta.to.shared.u64 t, %1; cvt.u32.u64 %0, t; }" : "=r"(a) : "l"(p));
    return a;
}

DEV_INLINE void ldmatrix_x4(uint32_t* r, uint32_t addr) {
    asm volatile("ldmatrix.sync.aligned.m8n8.x4.shared.b16 {%0,%1,%2,%3}, [%4];"
                 : "=r"(r[0]), "=r"(r[1]), "=r"(r[2]), "=r"(r[3]) : "r"(addr));
}

DEV_INLINE void mma16816(float* c, const uint32_t* a, uint32_t b0, uint32_t b1) {
    asm volatile(
        "mma.sync.aligned.m16n8k16.row.col.f32.bf16.bf16.f32 "
        "{%0,%1,%2,%3}, {%4,%5,%6,%7}, {%8,%9}, {%0,%1,%2,%3};"
        : "+f"(c[0]), "+f"(c[1]), "+f"(c[2]), "+f"(c[3])
        : "r"(a[0]), "r"(a[1]), "r"(a[2]), "r"(a[3]), "r"(b0), "r"(b1));
}

// ---------------- prep: normalize centers -> bf16 ----------------
__global__ void prep_centers_kernel(const float* __restrict__ cent) {
    int warp = (blockIdx.x * blockDim.x + threadIdx.x) >> 5;
    int lid  = threadIdx.x & 31;
    if (warp >= K_CENT) return;
    const float4 v = reinterpret_cast<const float4*>(cent + (size_t)warp * DIM)[lid];
    float s = v.x * v.x + v.y * v.y + v.z * v.z + v.w * v.w;
    #pragma unroll
    for (int o = 16; o; o >>= 1) s += __shfl_xor_sync(0xFFFFFFFFu, s, o);
    float inv = 1.0f / fmaxf(sqrtf(s), 1e-12f);
    __nv_bfloat162 p0 = __floats2bfloat162_rn(v.x * inv, v.y * inv);
    __nv_bfloat162 p1 = __floats2bfloat162_rn(v.z * inv, v.w * inv);
    uint2 pk;
    pk.x = *reinterpret_cast<uint32_t*>(&p0);
    pk.y = *reinterpret_cast<uint32_t*>(&p1);
    reinterpret_cast<uint2*>(g_cb + (size_t)warp * DIM)[lid] = pk;
}

// ---------------- fused: normalize features + sims GEMM + argmax ----------------
// Key trick: accumulators init to 2.0f so sim+2 in [1,3] (positive -> int-monotone).
// key = (float_bits & ~0x3FF) | (1023 - center_idx); integer max == argmax with
// smallest-index tie-break among ~2.4e-4-quantized ties.
__global__ void __launch_bounds__(256, 2) argmax_kernel(const float* __restrict__ feat) {
    extern __shared__ char smem[];
    char* As = smem;
    char* Bs = smem + SMEM_A_BYTES;
    const uint32_t a_s = smem_u32(As);
    const uint32_t b_s = smem_u32(Bs);

    const int tid  = threadIdx.x;
    const int w    = tid >> 5;
    const int lane = tid & 31;
    const size_t rowbase = (size_t)blockIdx.x * M_TILE;

    // ---- load + L2-normalize 32 rows per warp, store bf16 to smem ----
    #pragma unroll 4
    for (int r = 0; r < 32; r++) {
        const int row = w * 32 + r;
        const float4 v = reinterpret_cast<const float4*>(feat + (rowbase + row) * DIM)[lane];
        float s = v.x * v.x + v.y * v.y + v.z * v.z + v.w * v.w;
        #pragma unroll
        for (int o = 16; o; o >>= 1) s += __shfl_xor_sync(0xFFFFFFFFu, s, o);
        float inv = 1.0f / fmaxf(sqrtf(s), 1e-12f);
        __nv_bfloat162 p0 = __floats2bfloat162_rn(v.x * inv, v.y * inv);
        __nv_bfloat162 p1 = __floats2bfloat162_rn(v.z * inv, v.w * inv);
        uint2 pk;
        pk.x = *reinterpret_cast<uint32_t*>(&p0);
        pk.y = *reinterpret_cast<uint32_t*>(&p1);
        *reinterpret_cast<uint2*>(As + row * ROW_BYTES + lane * 8) = pk;
    }
    __syncthreads();

    // ---- A fragments: 2 m16 blocks x 8 k-steps x 4 regs (held in registers) ----
    uint32_t af[2][8][4];
    {
        const int rsel = lane & 15;
        const int cby  = (lane >> 4) * 16;
        #pragma unroll
        for (int mb = 0; mb < 2; mb++) {
            #pragma unroll
            for (int ks = 0; ks < 8; ks++) {
                uint32_t addr = a_s + (w * 32 + mb * 16 + rsel) * ROW_BYTES + ks * 32 + cby;
                ldmatrix_x4(af[mb][ks], addr);
            }
        }
    }

    int key[4];
    #pragma unroll
    for (int i = 0; i < 4; i++) key[i] = 0x80000000;

    const uint4* cb = reinterpret_cast<const uint4*>(g_cb);
    const uint32_t bfrag_base = b_s + (lane & 7) * ROW_BYTES + (lane >> 3) * 16;

    for (int c = 0; c < NUM_CHUNKS; c++) {
        // stage B chunk (128 centers x 128 bf16) into smem
        #pragma unroll
        for (int t = tid; t < 2048; t += 256) {
            const int row = t >> 4, j = t & 15;
            uint4 v = cb[(size_t)(c * NC_CHUNK + row) * 16 + j];
            *reinterpret_cast<uint4*>(Bs + row * ROW_BYTES + j * 16) = v;
        }
        __syncthreads();

        int codeA0 = 1023 - (c * NC_CHUNK + 2 * (lane & 3));

        #pragma unroll
        for (int nt = 0; nt < 16; nt++) {
            float c0[4] = {2.0f, 2.0f, 2.0f, 2.0f};
            float c1[4] = {2.0f, 2.0f, 2.0f, 2.0f};
            const uint32_t baddr = bfrag_base + nt * 8 * ROW_BYTES;

            #pragma unroll
            for (int kp = 0; kp < 4; kp++) {
                uint32_t b[4];
                ldmatrix_x4(b, baddr + kp * 64);
                mma16816(c0, af[0][2 * kp],     b[0], b[1]);
                mma16816(c0, af[0][2 * kp + 1], b[2], b[3]);
                mma16816(c1, af[1][2 * kp],     b[0], b[1]);
                mma16816(c1, af[1][2 * kp + 1], b[2], b[3]);
            }

            const int cA = codeA0 - nt * 8;
            const int cB = cA - 1;
            key[0] = max(key[0], (int)((__float_as_uint(c0[0]) & 0xFFFFFC00u) | (uint32_t)cA));
            key[0] = max(key[0], (int)((__float_as_uint(c0[1]) & 0xFFFFFC00u) | (uint32_t)cB));
            key[1] = max(key[1], (int)((__float_as_uint(c0[2]) & 0xFFFFFC00u) | (uint32_t)cA));
            key[1] = max(key[1], (int)((__float_as_uint(c0[3]) & 0xFFFFFC00u) | (uint32_t)cB));
            key[2] = max(key[2], (int)((__float_as_uint(c1[0]) & 0xFFFFFC00u) | (uint32_t)cA));
            key[2] = max(key[2], (int)((__float_as_uint(c1[1]) & 0xFFFFFC00u) | (uint32_t)cB));
            key[3] = max(key[3], (int)((__float_as_uint(c1[2]) & 0xFFFFFC00u) | (uint32_t)cA));
            key[3] = max(key[3], (int)((__float_as_uint(c1[3]) & 0xFFFFFC00u) | (uint32_t)cB));
        }
        __syncthreads();  // B chunk fully consumed before next overwrite
    }

    // reduce (value,idx) keys across the 4 lanes of each quad (cols live there)
    #pragma unroll
    for (int o = 1; o <= 2; o <<= 1) {
        #pragma unroll
        for (int i = 0; i < 4; i++)
            key[i] = max(key[i], __shfl_xor_sync(0xFFFFFFFFu, key[i], o));
    }
    if ((lane & 3) == 0) {
        const int r0 = (int)rowbase + w * 32 + (lane >> 2);
        g_assign[r0]      = 1023 - (key[0] & 1023);
        g_assign[r0 + 8]  = 1023 - (key[1] & 1023);
        g_assign[r0 + 16] = 1023 - (key[2] & 1023);
        g_assign[r0 + 24] = 1023 - (key[3] & 1023);
    }
}

// ---------------- loss: exact fp32 terms, fp64 partial sums ----------------
__global__ void loss_kernel(const float* __restrict__ feat, const float* __restrict__ cent) {
    __shared__ double wsum[8];
    const int wid = threadIdx.x >> 5;
    const int lid = threadIdx.x & 31;
    const int base = blockIdx.x * 256;

    double acc = 0.0;
    for (int it = 0; it < 32; it++) {
        const int r = base + it * 8 + wid;
        const float4 v = reinterpret_cast<const float4*>(feat + (size_t)r * DIM)[lid];
        float s = v.x * v.x + v.y * v.y + v.z * v.z + v.w * v.w;
        #pragma unroll
        for (int o = 16; o; o >>= 1) s += __shfl_xor_sync(0xFFFFFFFFu, s, o);
        float inv = 1.0f / fmaxf(sqrtf(s), 1e-12f);
        const int a = g_assign[r];
        const float4 cv = reinterpret_cast<const float4*>(cent + (size_t)a * DIM)[lid];
        float dx = v.x * inv - cv.x;
        float dy = v.y * inv - cv.y;
        float dz = v.z * inv - cv.z;
        float dw = v.w * inv - cv.w;
        float t = dx * dx + dy * dy + dz * dz + dw * dw;
        #pragma unroll
        for (int o = 16; o; o >>= 1) t += __shfl_xor_sync(0xFFFFFFFFu, t, o);
        if (lid == 0) acc += (double)t;
    }
    if (lid == 0) wsum[wid] = acc;
    __syncthreads();
    if (threadIdx.x == 0) {
        double s = 0.0;
        #pragma unroll
        for (int i = 0; i < 8; i++) s += wsum[i];
        g_partial[blockIdx.x] = s;  // plain write: deterministic across graph replays
    }
}

__global__ void finalize_kernel(float* __restrict__ out) {
    __shared__ double sh[LOSS_BLOCKS];
    sh[threadIdx.x] = g_partial[threadIdx.x];
    __syncthreads();
    for (int o = LOSS_BLOCKS / 2; o; o >>= 1) {
        if (threadIdx.x < o) sh[threadIdx.x] += sh[threadIdx.x + o];
        __syncthreads();
    }
    if (threadIdx.x == 0) out[0] = (float)(sh[0] / (double)N_FEAT);
}

// ---------------- launch ----------------
extern "C" void kernel_launch(void* const* d_in, const int* in_sizes, int n_in,
                              void* d_out, int out_size) {
    const float* feat = (const float*)d_in[0];
    const float* cent = (const float*)d_in[1];

    static bool attr_set = false;
    if (!attr_set) {
        cudaFuncSetAttribute(argmax_kernel, cudaFuncAttributeMaxDynamicSharedMemorySize, SMEM_TOTAL);
        attr_set = true;
    }

    prep_centers_kernel<<<K_CENT / 8, 256>>>(cent);
    argmax_kernel<<<N_FEAT / M_TILE, 256, SMEM_TOTAL>>>(feat);
    loss_kernel<<<LOSS_BLOCKS, 256>>>(feat, cent);
    finalize_kernel<<<1, LOSS_BLOCKS>>>((float*)d_out);
}